// round 14
// baseline (speedup 1.0000x reference)
#include <cuda_runtime.h>
#include <cuda_bf16.h>

#define H     128
#define NSEG  512
#define RANKS 3
#define LN_EPS 1e-5f
#define U     8      // rows per group in agg kernel
#define SEGT  8      // segments per block in proj kernel
#define AGG_BLOCKS 444   // 3 blocks/SM x 148 SMs -> persistent single wave
#define TILE  128    // rows per stolen work tile

// ---------------- scratch (no allocations allowed) ----------------
__device__ float g_sum [RANKS * NSEG * H];
__device__ float g_gsum[RANKS * NSEG * H];
__device__ float g_max [RANKS * NSEG * H];
__device__ float g_cnt [RANKS * NSEG];
__device__ float g_r   [RANKS * NSEG * H];
__device__ int   g_tile_ctr;

// ---------------- helpers ----------------
__device__ __forceinline__ void atomicMaxF(float* addr, float v) {
    if (v >= 0.f) atomicMax((int*)addr, __float_as_int(v));
    else          atomicMin((unsigned int*)addr, __float_as_uint(v));
}

__device__ __forceinline__ float warp_sum(float v) {
    v += __shfl_xor_sync(0xffffffffu, v, 16);
    v += __shfl_xor_sync(0xffffffffu, v, 8);
    v += __shfl_xor_sync(0xffffffffu, v, 4);
    v += __shfl_xor_sync(0xffffffffu, v, 2);
    v += __shfl_xor_sync(0xffffffffu, v, 1);
    return v;
}

__device__ __forceinline__ float silu(float x) {
    return x / (1.f + __expf(-x));
}

// ---------------- 1. zero accumulators + seed g_r with proj bias ----------------
__global__ void zero_kernel(const float* __restrict__ bp0,
                            const float* __restrict__ bp1,
                            const float* __restrict__ bp2) {
    int i = blockIdx.x * blockDim.x + threadIdx.x;
    if (i == 0) g_tile_ctr = 0;
    if (i < RANKS * NSEG * H) {
        g_sum[i]  = 0.f;
        g_gsum[i] = 0.f;
        g_max[i]  = __int_as_float(0xff800000);  // -inf
        const int rank = i / (NSEG * H);
        const int j    = i & (H - 1);
        const float* bp = (rank == 0) ? bp0 : (rank == 1) ? bp1 : bp2;
        g_r[i] = bp[j];
    }
    if (i < RANKS * NSEG) g_cnt[i] = 0.f;
}

// ---------------- 2. single-pass gated multi-aggregation ----------------
// Persistent warps steal 128-row tiles from a global counter (all ranks).
// Inner loop: 8-row groups, interleaved butterflies, boundary fast path.
__global__ __launch_bounds__(256, 3) void agg_kernel(
    const float* __restrict__ h0, const float* __restrict__ h1, const float* __restrict__ h2,
    const int*   __restrict__ b0, const int*   __restrict__ b1, const int*   __restrict__ b2,
    const float* __restrict__ Wg0, const float* __restrict__ Wg1, const float* __restrict__ Wg2,
    const float* __restrict__ bg0, const float* __restrict__ bg1, const float* __restrict__ bg2,
    int N0, int N1, int N2, int t0, int t01, int nTiles)
{
    const int lane = threadIdx.x & 31;
    const float NEG = __int_as_float(0xff800000);

    for (;;) {
        // steal a tile
        int tile;
        if (lane == 0) tile = atomicAdd(&g_tile_ctr, 1);
        tile = __shfl_sync(0xffffffffu, tile, 0);
        if (tile >= nTiles) break;

        int rank, lt;
        if (tile < t0)       { rank = 0; lt = tile; }
        else if (tile < t01) { rank = 1; lt = tile - t0; }
        else                 { rank = 2; lt = tile - t01; }

        const float* h;  const int* b;  const float* Wg;  float bg;  int N;
        if (rank == 0)      { h = h0; b = b0; Wg = Wg0; bg = bg0[0]; N = N0; }
        else if (rank == 1) { h = h1; b = b1; Wg = Wg1; bg = bg1[0]; N = N1; }
        else                { h = h2; b = b2; Wg = Wg2; bg = bg2[0]; N = N2; }

        const int start = lt * TILE;
        const int end   = min(start + TILE, N);
        if (start >= end) continue;

        const float4 wg = reinterpret_cast<const float4*>(Wg)[lane];

        float4 s  = make_float4(0.f, 0.f, 0.f, 0.f);
        float4 gs = make_float4(0.f, 0.f, 0.f, 0.f);
        float4 mx = make_float4(NEG, NEG, NEG, NEG);
        float  cnt = 0.f;
        int    cur = __ldg(&b[start]);

        #define FLUSH()                                                          \
        do {                                                                     \
            const int _base = (rank * NSEG + cur) * H + lane * 4;                \
            atomicAdd(&g_sum [_base + 0], s.x);  atomicAdd(&g_sum [_base + 1], s.y);  \
            atomicAdd(&g_sum [_base + 2], s.z);  atomicAdd(&g_sum [_base + 3], s.w);  \
            atomicAdd(&g_gsum[_base + 0], gs.x); atomicAdd(&g_gsum[_base + 1], gs.y); \
            atomicAdd(&g_gsum[_base + 2], gs.z); atomicAdd(&g_gsum[_base + 3], gs.w); \
            atomicMaxF(&g_max[_base + 0], mx.x); atomicMaxF(&g_max[_base + 1], mx.y); \
            atomicMaxF(&g_max[_base + 2], mx.z); atomicMaxF(&g_max[_base + 3], mx.w); \
            if (lane == 0) atomicAdd(&g_cnt[rank * NSEG + cur], cnt);            \
            s  = make_float4(0.f, 0.f, 0.f, 0.f);                                \
            gs = make_float4(0.f, 0.f, 0.f, 0.f);                                \
            mx = make_float4(NEG, NEG, NEG, NEG);                                \
            cnt = 0.f;                                                           \
        } while (0)

        int row = start;

        for (; row + U <= end; row += U) {
            float4 hv[U];
            float  p[U];
            const int4 bv0 = *reinterpret_cast<const int4*>(b + row);
            const int4 bv1 = *reinterpret_cast<const int4*>(b + row + 4);

            #pragma unroll
            for (int i = 0; i < U; ++i)
                hv[i] = reinterpret_cast<const float4*>(h + (size_t)(row + i) * H)[lane];

            #pragma unroll
            for (int i = 0; i < U; ++i)
                p[i] = hv[i].x * wg.x + hv[i].y * wg.y + hv[i].z * wg.z + hv[i].w * wg.w;

            #pragma unroll
            for (int off = 16; off; off >>= 1) {
                #pragma unroll
                for (int i = 0; i < U; ++i)
                    p[i] += __shfl_xor_sync(0xffffffffu, p[i], off);
            }

            if (bv1.w == cur) {
                #pragma unroll
                for (int i = 0; i < U; ++i) {
                    const float g = 1.f / (1.f + __expf(-(p[i] + bg)));
                    s.x += hv[i].x; s.y += hv[i].y; s.z += hv[i].z; s.w += hv[i].w;
                    gs.x = fmaf(g, hv[i].x, gs.x); gs.y = fmaf(g, hv[i].y, gs.y);
                    gs.z = fmaf(g, hv[i].z, gs.z); gs.w = fmaf(g, hv[i].w, gs.w);
                    mx.x = fmaxf(mx.x, hv[i].x);  mx.y = fmaxf(mx.y, hv[i].y);
                    mx.z = fmaxf(mx.z, hv[i].z);  mx.w = fmaxf(mx.w, hv[i].w);
                }
                cnt += (float)U;
            } else {
                int sg[U];
                sg[0] = bv0.x; sg[1] = bv0.y; sg[2] = bv0.z; sg[3] = bv0.w;
                sg[4] = bv1.x; sg[5] = bv1.y; sg[6] = bv1.z; sg[7] = bv1.w;
                #pragma unroll
                for (int i = 0; i < U; ++i) {
                    if (sg[i] != cur) { FLUSH(); cur = sg[i]; }
                    const float g = 1.f / (1.f + __expf(-(p[i] + bg)));
                    s.x += hv[i].x; s.y += hv[i].y; s.z += hv[i].z; s.w += hv[i].w;
                    gs.x = fmaf(g, hv[i].x, gs.x); gs.y = fmaf(g, hv[i].y, gs.y);
                    gs.z = fmaf(g, hv[i].z, gs.z); gs.w = fmaf(g, hv[i].w, gs.w);
                    mx.x = fmaxf(mx.x, hv[i].x);  mx.y = fmaxf(mx.y, hv[i].y);
                    mx.z = fmaxf(mx.z, hv[i].z);  mx.w = fmaxf(mx.w, hv[i].w);
                    cnt += 1.f;
                }
            }
        }

        for (; row < end; ++row) {
            float4 hv = reinterpret_cast<const float4*>(h + (size_t)row * H)[lane];
            int    sg = __ldg(&b[row]);
            if (sg != cur) { FLUSH(); cur = sg; }
            float p = hv.x * wg.x + hv.y * wg.y + hv.z * wg.z + hv.w * wg.w;
            p = warp_sum(p);
            const float g = 1.f / (1.f + __expf(-(p + bg)));
            s.x += hv.x; s.y += hv.y; s.z += hv.z; s.w += hv.w;
            gs.x = fmaf(g, hv.x, gs.x); gs.y = fmaf(g, hv.y, gs.y);
            gs.z = fmaf(g, hv.z, gs.z); gs.w = fmaf(g, hv.w, gs.w);
            mx.x = fmaxf(mx.x, hv.x);  mx.y = fmaxf(mx.y, hv.y);
            mx.z = fmaxf(mx.z, hv.z);  mx.w = fmaxf(mx.w, hv.w);
            cnt += 1.f;
        }

        FLUSH();
        #undef FLUSH
    }
}

// ---------------- 3. projection, split-k by aggregate type (unchanged) ----------------
__global__ __launch_bounds__(256) void proj_kernel(
    const float* __restrict__ Wp0,
    const float* __restrict__ Wp1,
    const float* __restrict__ Wp2)
{
    const int segBase = blockIdx.x * SEGT;
    const int q       = blockIdx.y;          // 0..3
    const int rank    = blockIdx.z;
    const int t       = threadIdx.x;

    const float* Wp = (rank == 0) ? Wp0 : (rank == 1) ? Wp1 : Wp2;

    __shared__ float sa[SEGT][H];

    for (int idx = t; idx < SEGT * H; idx += 256) {
        const int sl  = idx >> 7;
        const int jj  = idx & (H - 1);
        const int seg = segBase + sl;
        const int gb  = (rank * NSEG + seg) * H + jj;
        float val;
        if (q == 0)      val = g_sum[gb];
        else if (q == 1) val = g_sum[gb] / fmaxf(g_cnt[rank * NSEG + seg], 1.f);
        else if (q == 2) { const float mv = g_max[gb];
                           val = (g_cnt[rank * NSEG + seg] > 0.f) ? mv : 0.f; }
        else             val = g_gsum[gb];
        sa[sl][jj] = val;
    }
    __syncthreads();

    const int j   = t & (H - 1);
    const int sub = t >> 7;
    const int s0  = sub * 4;

    const float* wq = Wp + q * H * H + j;
    float a0 = 0.f, a1 = 0.f, a2 = 0.f, a3 = 0.f;
    #pragma unroll 4
    for (int k = 0; k < H; ++k) {
        const float wv = __ldg(&wq[k * H]);
        a0 = fmaf(sa[s0 + 0][k], wv, a0);
        a1 = fmaf(sa[s0 + 1][k], wv, a1);
        a2 = fmaf(sa[s0 + 2][k], wv, a2);
        a3 = fmaf(sa[s0 + 3][k], wv, a3);
    }

    const int gb = (rank * NSEG + segBase + s0) * H + j;
    atomicAdd(&g_r[gb],         a0);
    atomicAdd(&g_r[gb + H],     a1);
    atomicAdd(&g_r[gb + 2 * H], a2);
    atomicAdd(&g_r[gb + 3 * H], a3);
}

// ---------------- 4. head: 2 segs/block, 512 threads, 4-way k-split ----------------
// Each W1 load feeds both segments; W1 L2 traffic halves vs R9.
__global__ __launch_bounds__(512) void head_kernel(
    const float* __restrict__ gamma, const float* __restrict__ beta,
    const float* __restrict__ W1,    const float* __restrict__ b1f,
    const float* __restrict__ W2,    const float* __restrict__ b2f,
    float* __restrict__ out)
{
    const int t    = threadIdx.x;
    const int j    = t & (H - 1);
    const int qt   = t >> 7;                 // 0..3
    const int warp = t >> 5;                 // 0..15
    const int seg0 = blockIdx.x * 2;

    __shared__ float sx[2][3 * H];
    __shared__ float part[2][512];
    __shared__ float red[16][2];

    float v0[2], v1[2], v2[2];
    #pragma unroll
    for (int sl = 0; sl < 2; ++sl) {
        v0[sl] = g_r[(0 * NSEG + seg0 + sl) * H + j];
        v1[sl] = g_r[(1 * NSEG + seg0 + sl) * H + j];
        v2[sl] = g_r[(2 * NSEG + seg0 + sl) * H + j];
    }

    // mean for both segs (each element counted 4x across quarters)
    {
        float a = warp_sum(v0[0] + v1[0] + v2[0]);
        float c = warp_sum(v0[1] + v1[1] + v2[1]);
        if ((t & 31) == 0) { red[warp][0] = a; red[warp][1] = c; }
    }
    __syncthreads();
    float mu[2] = {0.f, 0.f};
    #pragma unroll
    for (int w = 0; w < 16; ++w) { mu[0] += red[w][0]; mu[1] += red[w][1]; }
    mu[0] *= (1.f / (4.f * 3.f * H));
    mu[1] *= (1.f / (4.f * 3.f * H));
    __syncthreads();

    // variance for both segs
    float d0[2], d1[2], d2[2];
    #pragma unroll
    for (int sl = 0; sl < 2; ++sl) {
        d0[sl] = v0[sl] - mu[sl]; d1[sl] = v1[sl] - mu[sl]; d2[sl] = v2[sl] - mu[sl];
    }
    {
        float a = warp_sum(d0[0]*d0[0] + d1[0]*d1[0] + d2[0]*d2[0]);
        float c = warp_sum(d0[1]*d0[1] + d1[1]*d1[1] + d2[1]*d2[1]);
        if ((t & 31) == 0) { red[warp][0] = a; red[warp][1] = c; }
    }
    __syncthreads();
    float rstd[2];
    {
        float va = 0.f, vb = 0.f;
        #pragma unroll
        for (int w = 0; w < 16; ++w) { va += red[w][0]; vb += red[w][1]; }
        rstd[0] = rsqrtf(va * (1.f / (4.f * 3.f * H)) + LN_EPS);
        rstd[1] = rsqrtf(vb * (1.f / (4.f * 3.f * H)) + LN_EPS);
    }
    __syncthreads();

    if (qt == 0) {
        const float ga0 = gamma[j], ga1 = gamma[H + j], ga2 = gamma[2 * H + j];
        const float be0 = beta[j],  be1 = beta[H + j],  be2 = beta[2 * H + j];
        #pragma unroll
        for (int sl = 0; sl < 2; ++sl) {
            sx[sl][j]         = silu(d0[sl] * rstd[sl] * ga0 + be0);
            sx[sl][H + j]     = silu(d1[sl] * rstd[sl] * ga1 + be1);
            sx[sl][2 * H + j] = silu(d2[sl] * rstd[sl] * ga2 + be2);
        }
    }
    __syncthreads();

    // x @ W1: quarter qt sums k in [qt*96, qt*96+96); each w feeds both segs
    const int k0 = qt * 96;
    float a0 = 0.f, a1 = 0.f, a2 = 0.f, a3 = 0.f;   // seg0
    float c0 = 0.f, c1 = 0.f, c2 = 0.f, c3 = 0.f;   // seg1
    #pragma unroll 4
    for (int k = 0; k < 96; k += 4) {
        const float w0 = W1[(k0 + k + 0) * H + j];
        const float w1 = W1[(k0 + k + 1) * H + j];
        const float w2 = W1[(k0 + k + 2) * H + j];
        const float w3 = W1[(k0 + k + 3) * H + j];
        a0 = fmaf(sx[0][k0 + k + 0], w0, a0);  c0 = fmaf(sx[1][k0 + k + 0], w0, c0);
        a1 = fmaf(sx[0][k0 + k + 1], w1, a1);  c1 = fmaf(sx[1][k0 + k + 1], w1, c1);
        a2 = fmaf(sx[0][k0 + k + 2], w2, a2);  c2 = fmaf(sx[1][k0 + k + 2], w2, c2);
        a3 = fmaf(sx[0][k0 + k + 3], w3, a3);  c3 = fmaf(sx[1][k0 + k + 3], w3, c3);
    }
    part[0][t] = (a0 + a1) + (a2 + a3);
    part[1][t] = (c0 + c1) + (c2 + c3);
    __syncthreads();

    // combine quarters -> SiLU -> dot with W2 (quarter 0 handles both segs)
    float oa = 0.f, ob = 0.f;
    if (qt == 0) {
        const float bb = b1f[j];
        const float w2 = W2[j];
        const float accA = part[0][j] + part[0][128 + j] + part[0][256 + j] + part[0][384 + j] + bb;
        const float accB = part[1][j] + part[1][128 + j] + part[1][256 + j] + part[1][384 + j] + bb;
        oa = silu(accA) * w2;
        ob = silu(accB) * w2;
    }
    oa = warp_sum(oa);
    ob = warp_sum(ob);
    if ((t & 31) == 0) { red[warp][0] = oa; red[warp][1] = ob; }
    __syncthreads();
    if (t < 2)
        out[seg0 + t] = red[0][t] + red[1][t] + red[2][t] + red[3][t] + b2f[0];
}

// ---------------- launcher ----------------
extern "C" void kernel_launch(void* const* d_in, const int* in_sizes, int n_in,
                              void* d_out, int out_size)
{
    const float* h0  = (const float*)d_in[0];
    const float* h1  = (const float*)d_in[1];
    const float* h2  = (const float*)d_in[2];
    const int*   b0  = (const int*)  d_in[3];
    const int*   b1  = (const int*)  d_in[4];
    const int*   b2  = (const int*)  d_in[5];
    const float* Wg0 = (const float*)d_in[6];
    const float* bg0 = (const float*)d_in[7];
    const float* Wg1 = (const float*)d_in[8];
    const float* bg1 = (const float*)d_in[9];
    const float* Wg2 = (const float*)d_in[10];
    const float* bg2 = (const float*)d_in[11];
    const float* Wp0 = (const float*)d_in[12];
    const float* bp0 = (const float*)d_in[13];
    const float* Wp1 = (const float*)d_in[14];
    const float* bp1 = (const float*)d_in[15];
    const float* Wp2 = (const float*)d_in[16];
    const float* bp2 = (const float*)d_in[17];
    const float* gamma = (const float*)d_in[18];
    const float* beta  = (const float*)d_in[19];
    const float* W1    = (const float*)d_in[20];
    const float* b1f   = (const float*)d_in[21];
    const float* W2    = (const float*)d_in[22];
    const float* b2f   = (const float*)d_in[23];

    const int N0 = in_sizes[3];
    const int N1 = in_sizes[4];
    const int N2 = in_sizes[5];

    // 1. zero segment accumulators; seed g_r with bp; reset tile counter
    zero_kernel<<<(RANKS * NSEG * H + 255) / 256, 256>>>(bp0, bp1, bp2);

    // 2. persistent work-stealing pass over all node features
    const int t0  = (N0 + TILE - 1) / TILE;
    const int t1  = (N1 + TILE - 1) / TILE;
    const int t2  = (N2 + TILE - 1) / TILE;
    const int nTiles = t0 + t1 + t2;
    agg_kernel<<<AGG_BLOCKS, 256>>>(h0, h1, h2, b0, b1, b2,
                                    Wg0, Wg1, Wg2, bg0, bg1, bg2,
                                    N0, N1, N2, t0, t0 + t1, nTiles);

    // 3. projection: split-k by aggregate type, atomic accumulation
    dim3 gProj(NSEG / SEGT, 4, RANKS);
    proj_kernel<<<gProj, 256>>>(Wp0, Wp1, Wp2);

    // 4. head (2 segs per block, 512 threads, 4-way k-split)
    head_kernel<<<NSEG / 2, 512>>>(gamma, beta, W1, b1f, W2, b2f, (float*)d_out);
}

// round 17
// speedup vs baseline: 1.1316x; 1.1316x over previous
#include <cuda_runtime.h>
#include <cuda_bf16.h>

#define H     128
#define NSEG  512
#define RANKS 3
#define LN_EPS 1e-5f
#define U     8      // rows per group in agg kernel
#define SEGT  8      // segments per block in proj kernel
#define AGG_BLOCKS 444   // 3 blocks/SM x 148 SMs -> persistent single wave
#define TILE  128    // rows per stolen work tile

// ---------------- scratch (no allocations allowed) ----------------
__device__ float g_sum [RANKS * NSEG * H];
__device__ float g_gsum[RANKS * NSEG * H];
__device__ float g_max [RANKS * NSEG * H];
__device__ float g_cnt [RANKS * NSEG];
__device__ float g_r   [RANKS * NSEG * H];
__device__ int   g_tile_ctr;

// ---------------- helpers ----------------
__device__ __forceinline__ void atomicMaxF(float* addr, float v) {
    if (v >= 0.f) atomicMax((int*)addr, __float_as_int(v));
    else          atomicMin((unsigned int*)addr, __float_as_uint(v));
}

__device__ __forceinline__ float warp_sum(float v) {
    v += __shfl_xor_sync(0xffffffffu, v, 16);
    v += __shfl_xor_sync(0xffffffffu, v, 8);
    v += __shfl_xor_sync(0xffffffffu, v, 4);
    v += __shfl_xor_sync(0xffffffffu, v, 2);
    v += __shfl_xor_sync(0xffffffffu, v, 1);
    return v;
}

__device__ __forceinline__ float silu(float x) {
    return x / (1.f + __expf(-x));
}

// ---------------- 1. zero accumulators + seed g_r with proj bias ----------------
__global__ void zero_kernel(const float* __restrict__ bp0,
                            const float* __restrict__ bp1,
                            const float* __restrict__ bp2) {
    int i = blockIdx.x * blockDim.x + threadIdx.x;
    if (i == 0) g_tile_ctr = 0;
    if (i < RANKS * NSEG * H) {
        g_sum[i]  = 0.f;
        g_gsum[i] = 0.f;
        g_max[i]  = __int_as_float(0xff800000);  // -inf
        const int rank = i / (NSEG * H);
        const int j    = i & (H - 1);
        const float* bp = (rank == 0) ? bp0 : (rank == 1) ? bp1 : bp2;
        g_r[i] = bp[j];
    }
    if (i < RANKS * NSEG) g_cnt[i] = 0.f;
}

// ---------------- 2. single-pass gated multi-aggregation ----------------
// Persistent warps steal 128-row tiles; __ldcs streaming loads (touch-once data).
__global__ __launch_bounds__(256, 3) void agg_kernel(
    const float* __restrict__ h0, const float* __restrict__ h1, const float* __restrict__ h2,
    const int*   __restrict__ b0, const int*   __restrict__ b1, const int*   __restrict__ b2,
    const float* __restrict__ Wg0, const float* __restrict__ Wg1, const float* __restrict__ Wg2,
    const float* __restrict__ bg0, const float* __restrict__ bg1, const float* __restrict__ bg2,
    int N0, int N1, int N2, int t0, int t01, int nTiles)
{
    const int lane = threadIdx.x & 31;
    const float NEG = __int_as_float(0xff800000);

    for (;;) {
        int tile;
        if (lane == 0) tile = atomicAdd(&g_tile_ctr, 1);
        tile = __shfl_sync(0xffffffffu, tile, 0);
        if (tile >= nTiles) break;

        int rank, lt;
        if (tile < t0)       { rank = 0; lt = tile; }
        else if (tile < t01) { rank = 1; lt = tile - t0; }
        else                 { rank = 2; lt = tile - t01; }

        const float* h;  const int* b;  const float* Wg;  float bg;  int N;
        if (rank == 0)      { h = h0; b = b0; Wg = Wg0; bg = bg0[0]; N = N0; }
        else if (rank == 1) { h = h1; b = b1; Wg = Wg1; bg = bg1[0]; N = N1; }
        else                { h = h2; b = b2; Wg = Wg2; bg = bg2[0]; N = N2; }

        const int start = lt * TILE;
        const int end   = min(start + TILE, N);
        if (start >= end) continue;

        const float4 wg = reinterpret_cast<const float4*>(Wg)[lane];

        float4 s  = make_float4(0.f, 0.f, 0.f, 0.f);
        float4 gs = make_float4(0.f, 0.f, 0.f, 0.f);
        float4 mx = make_float4(NEG, NEG, NEG, NEG);
        float  cnt = 0.f;
        int    cur = __ldg(&b[start]);

        #define FLUSH()                                                          \
        do {                                                                     \
            const int _base = (rank * NSEG + cur) * H + lane * 4;                \
            atomicAdd(&g_sum [_base + 0], s.x);  atomicAdd(&g_sum [_base + 1], s.y);  \
            atomicAdd(&g_sum [_base + 2], s.z);  atomicAdd(&g_sum [_base + 3], s.w);  \
            atomicAdd(&g_gsum[_base + 0], gs.x); atomicAdd(&g_gsum[_base + 1], gs.y); \
            atomicAdd(&g_gsum[_base + 2], gs.z); atomicAdd(&g_gsum[_base + 3], gs.w); \
            atomicMaxF(&g_max[_base + 0], mx.x); atomicMaxF(&g_max[_base + 1], mx.y); \
            atomicMaxF(&g_max[_base + 2], mx.z); atomicMaxF(&g_max[_base + 3], mx.w); \
            if (lane == 0) atomicAdd(&g_cnt[rank * NSEG + cur], cnt);            \
            s  = make_float4(0.f, 0.f, 0.f, 0.f);                                \
            gs = make_float4(0.f, 0.f, 0.f, 0.f);                                \
            mx = make_float4(NEG, NEG, NEG, NEG);                                \
            cnt = 0.f;                                                           \
        } while (0)

        int row = start;

        for (; row + U <= end; row += U) {
            float4 hv[U];
            float  p[U];
            const int4 bv0 = *reinterpret_cast<const int4*>(b + row);
            const int4 bv1 = *reinterpret_cast<const int4*>(b + row + 4);

            #pragma unroll
            for (int i = 0; i < U; ++i)
                hv[i] = __ldcs(reinterpret_cast<const float4*>(h + (size_t)(row + i) * H) + lane);

            #pragma unroll
            for (int i = 0; i < U; ++i)
                p[i] = hv[i].x * wg.x + hv[i].y * wg.y + hv[i].z * wg.z + hv[i].w * wg.w;

            #pragma unroll
            for (int off = 16; off; off >>= 1) {
                #pragma unroll
                for (int i = 0; i < U; ++i)
                    p[i] += __shfl_xor_sync(0xffffffffu, p[i], off);
            }

            if (bv1.w == cur) {
                #pragma unroll
                for (int i = 0; i < U; ++i) {
                    const float g = 1.f / (1.f + __expf(-(p[i] + bg)));
                    s.x += hv[i].x; s.y += hv[i].y; s.z += hv[i].z; s.w += hv[i].w;
                    gs.x = fmaf(g, hv[i].x, gs.x); gs.y = fmaf(g, hv[i].y, gs.y);
                    gs.z = fmaf(g, hv[i].z, gs.z); gs.w = fmaf(g, hv[i].w, gs.w);
                    mx.x = fmaxf(mx.x, hv[i].x);  mx.y = fmaxf(mx.y, hv[i].y);
                    mx.z = fmaxf(mx.z, hv[i].z);  mx.w = fmaxf(mx.w, hv[i].w);
                }
                cnt += (float)U;
            } else {
                int sg[U];
                sg[0] = bv0.x; sg[1] = bv0.y; sg[2] = bv0.z; sg[3] = bv0.w;
                sg[4] = bv1.x; sg[5] = bv1.y; sg[6] = bv1.z; sg[7] = bv1.w;
                #pragma unroll
                for (int i = 0; i < U; ++i) {
                    if (sg[i] != cur) { FLUSH(); cur = sg[i]; }
                    const float g = 1.f / (1.f + __expf(-(p[i] + bg)));
                    s.x += hv[i].x; s.y += hv[i].y; s.z += hv[i].z; s.w += hv[i].w;
                    gs.x = fmaf(g, hv[i].x, gs.x); gs.y = fmaf(g, hv[i].y, gs.y);
                    gs.z = fmaf(g, hv[i].z, gs.z); gs.w = fmaf(g, hv[i].w, gs.w);
                    mx.x = fmaxf(mx.x, hv[i].x);  mx.y = fmaxf(mx.y, hv[i].y);
                    mx.z = fmaxf(mx.z, hv[i].z);  mx.w = fmaxf(mx.w, hv[i].w);
                    cnt += 1.f;
                }
            }
        }

        for (; row < end; ++row) {
            float4 hv = __ldcs(reinterpret_cast<const float4*>(h + (size_t)row * H) + lane);
            int    sg = __ldg(&b[row]);
            if (sg != cur) { FLUSH(); cur = sg; }
            float p = hv.x * wg.x + hv.y * wg.y + hv.z * wg.z + hv.w * wg.w;
            p = warp_sum(p);
            const float g = 1.f / (1.f + __expf(-(p + bg)));
            s.x += hv.x; s.y += hv.y; s.z += hv.z; s.w += hv.w;
            gs.x = fmaf(g, hv.x, gs.x); gs.y = fmaf(g, hv.y, gs.y);
            gs.z = fmaf(g, hv.z, gs.z); gs.w = fmaf(g, hv.w, gs.w);
            mx.x = fmaxf(mx.x, hv.x);  mx.y = fmaxf(mx.y, hv.y);
            mx.z = fmaxf(mx.z, hv.z);  mx.w = fmaxf(mx.w, hv.w);
            cnt += 1.f;
        }

        FLUSH();
        #undef FLUSH
    }
}

// ---------------- 3. projection, split-k by aggregate type (unchanged) ----------------
__global__ __launch_bounds__(256) void proj_kernel(
    const float* __restrict__ Wp0,
    const float* __restrict__ Wp1,
    const float* __restrict__ Wp2)
{
    const int segBase = blockIdx.x * SEGT;
    const int q       = blockIdx.y;          // 0..3
    const int rank    = blockIdx.z;
    const int t       = threadIdx.x;

    const float* Wp = (rank == 0) ? Wp0 : (rank == 1) ? Wp1 : Wp2;

    __shared__ float sa[SEGT][H];

    for (int idx = t; idx < SEGT * H; idx += 256) {
        const int sl  = idx >> 7;
        const int jj  = idx & (H - 1);
        const int seg = segBase + sl;
        const int gb  = (rank * NSEG + seg) * H + jj;
        float val;
        if (q == 0)      val = g_sum[gb];
        else if (q == 1) val = g_sum[gb] / fmaxf(g_cnt[rank * NSEG + seg], 1.f);
        else if (q == 2) { const float mv = g_max[gb];
                           val = (g_cnt[rank * NSEG + seg] > 0.f) ? mv : 0.f; }
        else             val = g_gsum[gb];
        sa[sl][jj] = val;
    }
    __syncthreads();

    const int j   = t & (H - 1);
    const int sub = t >> 7;
    const int s0  = sub * 4;

    const float* wq = Wp + q * H * H + j;
    float a0 = 0.f, a1 = 0.f, a2 = 0.f, a3 = 0.f;
    #pragma unroll 4
    for (int k = 0; k < H; ++k) {
        const float wv = __ldg(&wq[k * H]);
        a0 = fmaf(sa[s0 + 0][k], wv, a0);
        a1 = fmaf(sa[s0 + 1][k], wv, a1);
        a2 = fmaf(sa[s0 + 2][k], wv, a2);
        a3 = fmaf(sa[s0 + 3][k], wv, a3);
    }

    const int gb = (rank * NSEG + segBase + s0) * H + j;
    atomicAdd(&g_r[gb],         a0);
    atomicAdd(&g_r[gb + H],     a1);
    atomicAdd(&g_r[gb + 2 * H], a2);
    atomicAdd(&g_r[gb + 3 * H], a3);
}

// ---------------- 4. head: R9 measured-best (1 seg/block, 512 thr, fp32 W1) ----------------
__global__ __launch_bounds__(512) void head_kernel(
    const float* __restrict__ gamma, const float* __restrict__ beta,
    const float* __restrict__ W1,    const float* __restrict__ b1f,
    const float* __restrict__ W2,    const float* __restrict__ b2f,
    float* __restrict__ out)
{
    const int seg  = blockIdx.x;
    const int t    = threadIdx.x;
    const int j    = t & (H - 1);
    const int qt   = t >> 7;                 // 0..3
    const int warp = t >> 5;                 // 0..15

    __shared__ float sx[3 * H];
    __shared__ float part[512];
    __shared__ float red[16];

    const float v0 = g_r[(0 * NSEG + seg) * H + j];
    const float v1 = g_r[(1 * NSEG + seg) * H + j];
    const float v2 = g_r[(2 * NSEG + seg) * H + j];

    // mean (each element counted 4x across quarters)
    float loc = warp_sum(v0 + v1 + v2);
    if ((t & 31) == 0) red[warp] = loc;
    __syncthreads();
    float tot = 0.f;
    #pragma unroll
    for (int w = 0; w < 16; ++w) tot += red[w];
    const float mu = tot * (1.f / (4.f * 3.f * H));
    __syncthreads();

    // variance (also 4x)
    const float d0 = v0 - mu, d1 = v1 - mu, d2 = v2 - mu;
    float loc2 = warp_sum(d0 * d0 + d1 * d1 + d2 * d2);
    if ((t & 31) == 0) red[warp] = loc2;
    __syncthreads();
    float tot2 = 0.f;
    #pragma unroll
    for (int w = 0; w < 16; ++w) tot2 += red[w];
    const float var  = tot2 * (1.f / (4.f * 3.f * H));
    const float rstd = rsqrtf(var + LN_EPS);
    __syncthreads();

    if (qt == 0) {
        const float xn0 = d0 * rstd * gamma[j]         + beta[j];
        const float xn1 = d1 * rstd * gamma[H + j]     + beta[H + j];
        const float xn2 = d2 * rstd * gamma[2 * H + j] + beta[2 * H + j];
        sx[j]         = silu(xn0);
        sx[H + j]     = silu(xn1);
        sx[2 * H + j] = silu(xn2);
    }
    __syncthreads();

    // x @ W1: quarter qt sums k in [qt*96, qt*96+96), 4 accumulators
    const int k0 = qt * 96;
    float a0 = 0.f, a1 = 0.f, a2 = 0.f, a3 = 0.f;
    #pragma unroll 4
    for (int k = 0; k < 96; k += 4) {
        a0 = fmaf(sx[k0 + k + 0], W1[(k0 + k + 0) * H + j], a0);
        a1 = fmaf(sx[k0 + k + 1], W1[(k0 + k + 1) * H + j], a1);
        a2 = fmaf(sx[k0 + k + 2], W1[(k0 + k + 2) * H + j], a2);
        a3 = fmaf(sx[k0 + k + 3], W1[(k0 + k + 3) * H + j], a3);
    }
    part[t] = (a0 + a1) + (a2 + a3);
    __syncthreads();

    // combine quarters -> SiLU -> dot with W2 (quarter 0 only)
    float o = 0.f;
    if (qt == 0) {
        const float acc = part[j] + part[128 + j] + part[256 + j] + part[384 + j] + b1f[j];
        o = silu(acc) * W2[j];
    }
    o = warp_sum(o);
    if ((t & 31) == 0) red[warp] = o;
    __syncthreads();
    if (t == 0)
        out[seg] = red[0] + red[1] + red[2] + red[3] + b2f[0];
}

// ---------------- launcher ----------------
extern "C" void kernel_launch(void* const* d_in, const int* in_sizes, int n_in,
                              void* d_out, int out_size)
{
    const float* h0  = (const float*)d_in[0];
    const float* h1  = (const float*)d_in[1];
    const float* h2  = (const float*)d_in[2];
    const int*   b0  = (const int*)  d_in[3];
    const int*   b1  = (const int*)  d_in[4];
    const int*   b2  = (const int*)  d_in[5];
    const float* Wg0 = (const float*)d_in[6];
    const float* bg0 = (const float*)d_in[7];
    const float* Wg1 = (const float*)d_in[8];
    const float* bg1 = (const float*)d_in[9];
    const float* Wg2 = (const float*)d_in[10];
    const float* bg2 = (const float*)d_in[11];
    const float* Wp0 = (const float*)d_in[12];
    const float* bp0 = (const float*)d_in[13];
    const float* Wp1 = (const float*)d_in[14];
    const float* bp1 = (const float*)d_in[15];
    const float* Wp2 = (const float*)d_in[16];
    const float* bp2 = (const float*)d_in[17];
    const float* gamma = (const float*)d_in[18];
    const float* beta  = (const float*)d_in[19];
    const float* W1    = (const float*)d_in[20];
    const float* b1f   = (const float*)d_in[21];
    const float* W2    = (const float*)d_in[22];
    const float* b2f   = (const float*)d_in[23];

    const int N0 = in_sizes[3];
    const int N1 = in_sizes[4];
    const int N2 = in_sizes[5];

    // 1. zero segment accumulators; seed g_r with bp; reset tile counter
    zero_kernel<<<(RANKS * NSEG * H + 255) / 256, 256>>>(bp0, bp1, bp2);

    // 2. persistent work-stealing pass over all node features (__ldcs streams)
    const int t0  = (N0 + TILE - 1) / TILE;
    const int t1  = (N1 + TILE - 1) / TILE;
    const int t2  = (N2 + TILE - 1) / TILE;
    const int nTiles = t0 + t1 + t2;
    agg_kernel<<<AGG_BLOCKS, 256>>>(h0, h1, h2, b0, b1, b2,
                                    Wg0, Wg1, Wg2, bg0, bg1, bg2,
                                    N0, N1, N2, t0, t0 + t1, nTiles);

    // 3. projection: split-k by aggregate type, atomic accumulation
    dim3 gProj(NSEG / SEGT, 4, RANKS);
    proj_kernel<<<gProj, 256>>>(Wp0, Wp1, Wp2);

    // 4. head (R9 measured-best, fp32 W1)
    head_kernel<<<NSEG, 512>>>(gamma, beta, W1, b1f, W2, b2f, (float*)d_out);
}